// round 2
// baseline (speedup 1.0000x reference)
#include <cuda_runtime.h>
#include <cuda_pipeline.h>
#include <cstdint>

// Problem constants
#define B_TOT 4096
#define SEQ   50
#define HID   256
#define G3    1536        // per-k row in WT: [ih_r|ih_z|ih_n|hh_r|hh_z|hh_n] = 2*768
#define TB    32          // batch rows per CTA
#define NCTA  (B_TOT / TB)  // 128
#define NT    256         // threads per CTA
#define KT    8           // k per tile
#define NTILE (HID / KT)  // 32

// smem layout (float offsets)
#define OFF_SWT 0                       // [2][KT][G3] = 24576
#define OFF_SHC 24576                   // [256][36]   = 9216  (C_s transposed, padded)
#define OFF_SHH 33792                   // [2][256][36] = 18432 (h double buffer, transposed)
#define OFF_SB  52224                   // [4][256] combined biases: r, z, in, hn
#define OFF_SG  53248                   // [32] gate G per step
#define SMEM_FLOATS 53280
#define SMEM_BYTES  (SMEM_FLOATS * 4)   // 213120 < 227KB

// W pre-transposed: WT[k*1536 + g], g<768 -> W_ih[g][k], else W_hh[g-768][k]
__device__ float g_WT[HID * G3];

__device__ __forceinline__ void fma2(unsigned long long& d,
                                     unsigned long long a,
                                     unsigned long long b) {
    asm("fma.rn.f32x2 %0, %1, %2, %0;" : "+l"(d) : "l"(a), "l"(b));
}
__device__ __forceinline__ unsigned long long splat2(float v) {
    unsigned long long r;
    asm("mov.b64 %0, {%1, %1};" : "=l"(r) : "f"(v));
    return r;
}
__device__ __forceinline__ void unpack2(unsigned long long v, float& lo, float& hi) {
    asm("mov.b64 {%0, %1}, %2;" : "=f"(lo), "=f"(hi) : "l"(v));
}

__device__ __forceinline__ float gru_cell(float xr, float xz, float xin, float xhn,
                                          float hprev, float g) {
    float r = __fdividef(1.f, 1.f + __expf(-xr));
    float z = __fdividef(1.f, 1.f + __expf(-xz));
    float t = xin + r * xhn;
    t = fminf(fmaxf(t, -30.f), 30.f);
    float e = __expf(-2.f * t);
    float n = __fdividef(1.f - e, 1.f + e);
    float hnew = (1.f - z) * n + z * hprev;
    return g * hnew + (1.f - g) * hprev;
}

__global__ void transpose_w_kernel(const float* __restrict__ Wih,
                                   const float* __restrict__ Whh) {
    int idx = blockIdx.x * 256 + threadIdx.x;   // 1536 blocks * 256 = 393216
    int g = idx % G3;
    int k = idx / G3;
    float v = (g < 768) ? Wih[g * HID + k] : Whh[(g - 768) * HID + k];
    g_WT[idx] = v;
}

__global__ void __launch_bounds__(NT, 1)
gru_kernel(const float* __restrict__ C, const float* __restrict__ G,
           const float* __restrict__ b_ih, const float* __restrict__ b_hh,
           float* __restrict__ out)
{
    extern __shared__ float sm[];
    const int tid = threadIdx.x;
    const int jt  = tid & 63;     // 64 j-threads, 4 j each -> 256 hidden
    const int bg  = tid >> 6;     // 4 b-groups, 8 b each   -> 32 batch rows
    const int j0  = jt * 4;
    const int b0  = bg * 8;
    const int bbase = blockIdx.x * TB;

    // combined biases into smem
    for (int i = tid; i < HID; i += NT) {
        sm[OFF_SB + i]         = b_ih[i]        + b_hh[i];
        sm[OFF_SB + 256 + i]   = b_ih[256 + i]  + b_hh[256 + i];
        sm[OFF_SB + 512 + i]   = b_ih[512 + i];
        sm[OFF_SB + 768 + i]   = b_hh[512 + i];
    }
    // h0 = 0 (buffer 0)
    for (int i = tid; i < 256 * 36; i += NT) sm[OFF_SHH + i] = 0.f;

    int ph = 0;

    #pragma unroll 1
    for (int s = 0; s < SEQ; ++s) {
        // ---- stage C[:, s, :] transposed into SHC (padded rows of 36) ----
        #pragma unroll
        for (int i = 0; i < 8; ++i) {
            int f = i * 1024 + tid * 4;     // 8192 floats
            int b = f >> 8;
            int h = f & 255;
            float4 v = *reinterpret_cast<const float4*>(
                C + ((size_t)(bbase + b) * SEQ + s) * HID + h);
            sm[OFF_SHC + (h + 0) * 36 + b] = v.x;
            sm[OFF_SHC + (h + 1) * 36 + b] = v.y;
            sm[OFF_SHC + (h + 2) * 36 + b] = v.z;
            sm[OFF_SHC + (h + 3) * 36 + b] = v.w;
        }
        if (tid < TB) sm[OFF_SG + tid] = G[(size_t)(bbase + tid) * SEQ + s];

        // ---- prefetch W tile 0 into buffer 0 ----
        #pragma unroll
        for (int i = 0; i < 12; ++i) {
            int f = i * 1024 + tid * 4;     // 12288 floats = KT*G3
            __pipeline_memcpy_async(&sm[OFF_SWT + f], &g_WT[f], 16);
        }
        __pipeline_commit();
        __pipeline_wait_prior(0);
        __syncthreads();

        // ---- init accumulators from biases (packed f32x2 pairs over j) ----
        unsigned long long ar[8][2], az[8][2], ain[8][2], ahn[8][2];
        {
            unsigned long long br0 = *(const unsigned long long*)&sm[OFF_SB + j0];
            unsigned long long br1 = *(const unsigned long long*)&sm[OFF_SB + j0 + 2];
            unsigned long long bz0 = *(const unsigned long long*)&sm[OFF_SB + 256 + j0];
            unsigned long long bz1 = *(const unsigned long long*)&sm[OFF_SB + 256 + j0 + 2];
            unsigned long long bi0 = *(const unsigned long long*)&sm[OFF_SB + 512 + j0];
            unsigned long long bi1 = *(const unsigned long long*)&sm[OFF_SB + 512 + j0 + 2];
            unsigned long long bh0 = *(const unsigned long long*)&sm[OFF_SB + 768 + j0];
            unsigned long long bh1 = *(const unsigned long long*)&sm[OFF_SB + 768 + j0 + 2];
            #pragma unroll
            for (int bb = 0; bb < 8; ++bb) {
                ar[bb][0] = br0;  ar[bb][1] = br1;
                az[bb][0] = bz0;  az[bb][1] = bz1;
                ain[bb][0] = bi0; ain[bb][1] = bi1;
                ahn[bb][0] = bh0; ahn[bb][1] = bh1;
            }
        }

        const float* shh = sm + OFF_SHH + ph * 9216;

        // ---- K loop: 32 tiles of 8, double-buffered W via cp.async ----
        int buf = 0;
        #pragma unroll 1
        for (int kt = 0; kt < NTILE; ++kt) {
            if (kt + 1 < NTILE) {
                const float* src = g_WT + (size_t)(kt + 1) * (KT * G3);
                float* dst = sm + OFF_SWT + (buf ^ 1) * (KT * G3);
                #pragma unroll
                for (int i = 0; i < 12; ++i) {
                    int f = i * 1024 + tid * 4;
                    __pipeline_memcpy_async(dst + f, src + f, 16);
                }
                __pipeline_commit();
            }
            const float* wt = sm + OFF_SWT + buf * (KT * G3);
            #pragma unroll
            for (int kk = 0; kk < KT; ++kk) {
                const int k = kt * KT + kk;
                const float* wrow = wt + kk * G3;
                ulonglong2 wir = *(const ulonglong2*)(wrow + j0);
                ulonglong2 wiz = *(const ulonglong2*)(wrow + 256 + j0);
                ulonglong2 win = *(const ulonglong2*)(wrow + 512 + j0);
                ulonglong2 whr = *(const ulonglong2*)(wrow + 768 + j0);
                ulonglong2 whz = *(const ulonglong2*)(wrow + 1024 + j0);
                ulonglong2 whn = *(const ulonglong2*)(wrow + 1280 + j0);
                float4 c0 = *(const float4*)(sm + OFF_SHC + k * 36 + b0);
                float4 c1 = *(const float4*)(sm + OFF_SHC + k * 36 + b0 + 4);
                float4 h0 = *(const float4*)(shh + k * 36 + b0);
                float4 h1 = *(const float4*)(shh + k * 36 + b0 + 4);
                float cs[8] = {c0.x, c0.y, c0.z, c0.w, c1.x, c1.y, c1.z, c1.w};
                float hs[8] = {h0.x, h0.y, h0.z, h0.w, h1.x, h1.y, h1.z, h1.w};
                #pragma unroll
                for (int bb = 0; bb < 8; ++bb) {
                    unsigned long long c2 = splat2(cs[bb]);
                    unsigned long long h2 = splat2(hs[bb]);
                    fma2(ar[bb][0],  c2, wir.x);  fma2(ar[bb][1],  c2, wir.y);
                    fma2(ar[bb][0],  h2, whr.x);  fma2(ar[bb][1],  h2, whr.y);
                    fma2(az[bb][0],  c2, wiz.x);  fma2(az[bb][1],  c2, wiz.y);
                    fma2(az[bb][0],  h2, whz.x);  fma2(az[bb][1],  h2, whz.y);
                    fma2(ain[bb][0], c2, win.x);  fma2(ain[bb][1], c2, win.y);
                    fma2(ahn[bb][0], h2, whn.x);  fma2(ahn[bb][1], h2, whn.y);
                }
            }
            if (kt + 1 < NTILE) __pipeline_wait_prior(0);
            __syncthreads();
            buf ^= 1;
        }

        // ---- epilogue: gates, h update, gated output; write to other h buffer ----
        float* shn = sm + OFF_SHH + (ph ^ 1) * 9216;
        #pragma unroll
        for (int p = 0; p < 2; ++p) {
            const int jA = j0 + 2 * p;
            const int jB = jA + 1;
            float4 hA0 = *(const float4*)(shh + jA * 36 + b0);
            float4 hA1 = *(const float4*)(shh + jA * 36 + b0 + 4);
            float4 hB0 = *(const float4*)(shh + jB * 36 + b0);
            float4 hB1 = *(const float4*)(shh + jB * 36 + b0 + 4);
            float holdA[8] = {hA0.x, hA0.y, hA0.z, hA0.w, hA1.x, hA1.y, hA1.z, hA1.w};
            float holdB[8] = {hB0.x, hB0.y, hB0.z, hB0.w, hB1.x, hB1.y, hB1.z, hB1.w};
            float resA[8], resB[8];
            #pragma unroll
            for (int bb = 0; bb < 8; ++bb) {
                float r0, r1, z0, z1, i0, i1, n0, n1;
                unpack2(ar[bb][p],  r0, r1);
                unpack2(az[bb][p],  z0, z1);
                unpack2(ain[bb][p], i0, i1);
                unpack2(ahn[bb][p], n0, n1);
                float g = sm[OFF_SG + b0 + bb];
                resA[bb] = gru_cell(r0, z0, i0, n0, holdA[bb], g);
                resB[bb] = gru_cell(r1, z1, i1, n1, holdB[bb], g);
            }
            *(float4*)(shn + jA * 36 + b0)     = make_float4(resA[0], resA[1], resA[2], resA[3]);
            *(float4*)(shn + jA * 36 + b0 + 4) = make_float4(resA[4], resA[5], resA[6], resA[7]);
            *(float4*)(shn + jB * 36 + b0)     = make_float4(resB[0], resB[1], resB[2], resB[3]);
            *(float4*)(shn + jB * 36 + b0 + 4) = make_float4(resB[4], resB[5], resB[6], resB[7]);
        }
        __syncthreads();
        ph ^= 1;
    }

    // ---- write final h: out[(bbase+b)*256 + j], thread tid = j ----
    const float* hf = sm + OFF_SHH + ph * 9216;
    #pragma unroll
    for (int i = 0; i < TB; ++i) {
        out[(size_t)(bbase + i) * HID + tid] = hf[tid * 36 + i];
    }
}

extern "C" void kernel_launch(void* const* d_in, const int* in_sizes, int n_in,
                              void* d_out, int out_size) {
    const float* C   = (const float*)d_in[0];
    const float* G   = (const float*)d_in[1];
    const float* Wih = (const float*)d_in[2];
    const float* Whh = (const float*)d_in[3];
    const float* bih = (const float*)d_in[4];
    const float* bhh = (const float*)d_in[5];
    float* out = (float*)d_out;

    cudaFuncSetAttribute(gru_kernel, cudaFuncAttributeMaxDynamicSharedMemorySize,
                         SMEM_BYTES);

    transpose_w_kernel<<<1536, 256>>>(Wih, Whh);
    gru_kernel<<<NCTA, NT, SMEM_BYTES>>>(C, G, bih, bhh, out);
}